// round 17
// baseline (speedup 1.0000x reference)
#include <cuda_runtime.h>
#include <cuda_bf16.h>
#include <math.h>
#include <stdint.h>

// ---------------- problem constants ----------------
#define NN 100000
#define EE 3200000
#define HH 64
#define DD 256

// ---------------- scratch (device globals; no runtime alloc) ----------------
__device__ __align__(128) float g_xu[NN * HH];
__device__ __align__(128) float g_su[NN * HH];
__device__ __align__(128) float g_ew[EE];
__device__ __align__(128) float g_m[NN];
__device__ __align__(128) float g_denom[NN];
__device__ __align__(128) float g_agg[NN * HH];
__device__ __align__(128) float g_h1[NN * HH];
__device__ __align__(128) float g_t2[NN * DD];
__device__ __align__(128) float g_t3[NN * DD];
__device__ __align__(16) float g_C[HH * HH];
__device__ __align__(16) float g_A12[2 * HH * HH];   // [Minv ; C@Minv] (128 x 64)
__device__ float g_ssum[4 * DD];                      // 4 BN stat slots
__device__ float g_ssq[4 * DD];
__device__ int g_idx64;

// bf16 hi/lo transposed weights [CO, K]
__device__ __align__(128) __nv_bfloat16 g_WuhT[HH * DD], g_WulT[HH * DD];
__device__ __align__(128) __nv_bfloat16 g_WphT[HH * DD], g_WplT[HH * DD];
__device__ __align__(128) __nv_bfloat16 g_A12hT[HH * 2 * HH], g_A12lT[HH * 2 * HH];
__device__ __align__(128) __nv_bfloat16 g_WmhT[DD * HH], g_WmlT[DD * HH];
__device__ __align__(128) __nv_bfloat16 g_WfhT[DD * 2 * DD], g_WflT[DD * 2 * DD];

// ---------------- index dtype handling ----------------
__global__ void k_detect(const unsigned int* p) {
    if (threadIdx.x == 0 && blockIdx.x == 0) {
        int is64 = 1;
        for (int k = 1; k < 64; k += 2) {
            if (p[k] != 0u) { is64 = 0; break; }
        }
        g_idx64 = is64;
    }
}
__device__ __forceinline__ int load_idx(const void* p, long k) {
    if (g_idx64) return (int)(((const long long*)p)[k]);
    return ((const int*)p)[k];
}

// ---------------- init (also zeroes all 4 BN stat slots) ----------------
__global__ void k_init(int n) {
    long a = (long)n * HH;
    long total = a + 2L * n + 8L * DD;
    long idx = (long)blockIdx.x * blockDim.x + threadIdx.x;
    if (idx >= total) return;
    if (idx < a) {
        g_agg[idx] = 0.0f;
    } else if (idx < a + n) {
        g_denom[idx - a] = 0.0f;
    } else if (idx < a + 2L * n) {
        ((unsigned int*)g_m)[idx - a - n] = 0xFF800000u;  // -inf
    } else {
        long s = idx - a - 2L * n;
        if (s < 4 * DD) g_ssum[s] = 0.0f;
        else g_ssq[s - 4 * DD] = 0.0f;
    }
}

// ---------------- CRF matrix prep ----------------
__global__ void k_prep_crf(const float* __restrict__ c) {
    __shared__ __align__(16) float Maug[HH][2 * HH + 1];
    int tid = threadIdx.x;
    for (int idx = tid; idx < HH * HH; idx += 256) {
        int a = idx >> 6, b = idx & 63;
        float s = 0.0f;
        for (int k = 0; k < HH; k++) s += c[k * HH + a] * c[k * HH + b];
        g_C[idx] = s;
        Maug[a][b] = s + (a == b ? 1.0f : 0.0f);
        Maug[a][HH + b] = (a == b ? 1.0f : 0.0f);
    }
    __syncthreads();
    for (int p = 0; p < HH; p++) {
        float pinv = 1.0f / Maug[p][p];
        __syncthreads();
        if (tid < 2 * HH) Maug[p][tid] *= pinv;
        __syncthreads();
        int r = tid & 63, cs = tid >> 6;
        float f = (r != p) ? Maug[r][p] : 0.0f;
        __syncthreads();
        if (r != p) {
            #pragma unroll 8
            for (int q = 0; q < 32; q++) {
                int col = cs * 32 + q;
                Maug[r][col] -= f * Maug[p][col];
            }
        }
        __syncthreads();
    }
    for (int idx = tid; idx < HH * HH; idx += 256) {
        int a = idx >> 6, b = idx & 63;
        g_A12[idx] = Maug[a][HH + b];
    }
    __syncthreads();
    for (int idx = tid; idx < HH * HH; idx += 256) {
        int a = idx >> 6, b = idx & 63;
        float s = 0.0f;
        for (int k = 0; k < HH; k++) s += g_C[a * HH + k] * Maug[k][HH + b];
        g_A12[HH * HH + idx] = s;
    }
}

// ---------------- weight prep: W[K,CO] fp32 -> hi/lo bf16 transposed [CO,K] ----
template <int K, int CO>
__global__ void k_wprep(const float* __restrict__ W,
                        __nv_bfloat16* __restrict__ hT, __nv_bfloat16* __restrict__ lT) {
    int idx = blockIdx.x * 256 + threadIdx.x;
    if (idx >= K * CO) return;
    int co = idx / K, k = idx % K;
    float w = W[(long)k * CO + co];
    __nv_bfloat16 h = __float2bfloat16(w);
    hT[idx] = h;
    lT[idx] = __float2bfloat16(w - __bfloat162float(h));
}

// ---------------- mma.sync + ldmatrix helpers ----------------
__device__ __forceinline__ void mma16816(float* d, const uint32_t* a, const uint32_t* b) {
    asm volatile(
        "mma.sync.aligned.m16n8k16.row.col.f32.bf16.bf16.f32 "
        "{%0,%1,%2,%3}, {%4,%5,%6,%7}, {%8,%9}, {%0,%1,%2,%3};"
        : "+f"(d[0]), "+f"(d[1]), "+f"(d[2]), "+f"(d[3])
        : "r"(a[0]), "r"(a[1]), "r"(a[2]), "r"(a[3]), "r"(b[0]), "r"(b[1]));
}
__device__ __forceinline__ void ldmx4(uint32_t* r, const void* p) {
    uint32_t addr = (uint32_t)__cvta_generic_to_shared(p);
    asm volatile("ldmatrix.sync.aligned.m8n8.x4.shared.b16 {%0,%1,%2,%3}, [%4];"
                 : "=r"(r[0]), "=r"(r[1]), "=r"(r[2]), "=r"(r[3]) : "r"(addr));
}

// ---------------- split-bf16 tensor-core GEMM via mma.sync + ldmatrix ----------
template <int K, int CO, bool CONCAT, bool SCALE2>
__global__ __launch_bounds__(256) void k_mm(
    const float* __restrict__ A, const float* __restrict__ A2s,
    const __nv_bfloat16* __restrict__ BhT, const __nv_bfloat16* __restrict__ BlT,
    float* __restrict__ out, int n)
{
    constexpr int LDS = 40;
    constexpr int NCH = K / 32;
    __shared__ __align__(16) __nv_bfloat16 Ah[128 * LDS], Al[128 * LDS];
    __shared__ __align__(16) __nv_bfloat16 Bh[64 * LDS], Bl[64 * LDS];

    int tid = threadIdx.x;
    int wid = tid >> 5, lane = tid & 31;
    int wm = wid >> 1, wn = wid & 1;
    int g = lane >> 2, tg = lane & 3;
    int row0 = blockIdx.x * 128;
    int col0 = blockIdx.y * 64;

    int quad = lane >> 3, tr = lane & 7;
    int rsel = (quad & 1) * 8 + tr;
    int csel = (quad >> 1) * 8;

    float d[2][4][4];
    #pragma unroll
    for (int mt = 0; mt < 2; mt++)
        #pragma unroll
        for (int nt = 0; nt < 4; nt++)
            #pragma unroll
            for (int q = 0; q < 4; q++) d[mt][nt][q] = 0.0f;

    int arow = tid >> 1;
    int ahalf = (tid & 1) * 16;
    int brow = tid >> 2;
    int bseg = (tid & 3) * 8;

    for (int ch = 0; ch < NCH; ch++) {
        int k0 = ch * 32;
        __syncthreads();
        {
            int grow = row0 + arow;
            int gk = k0 + ahalf;
            const float* src = A;
            int stride = K;
            bool second = false;
            if (CONCAT) {
                stride = K / 2;
                if (gk >= K / 2) { src = A2s; gk -= K / 2; second = true; }
            }
            float f[16];
            if (grow < n) {
                #pragma unroll
                for (int q4 = 0; q4 < 4; q4++) {
                    float4 v = *(const float4*)(src + (long)grow * stride + gk + q4 * 4);
                    f[q4 * 4 + 0] = v.x; f[q4 * 4 + 1] = v.y;
                    f[q4 * 4 + 2] = v.z; f[q4 * 4 + 3] = v.w;
                }
                if (SCALE2 && second) {
                    float rs = 1.0f / (g_denom[grow] + 1e-16f);
                    #pragma unroll
                    for (int q = 0; q < 16; q++) f[q] *= rs;
                }
            } else {
                #pragma unroll
                for (int q = 0; q < 16; q++) f[q] = 0.0f;
            }
            union { __nv_bfloat16 b[16]; uint4 u4[2]; } Uh, Ul;
            #pragma unroll
            for (int q = 0; q < 16; q++) {
                __nv_bfloat16 h = __float2bfloat16(f[q]);
                Uh.b[q] = h;
                Ul.b[q] = __float2bfloat16(f[q] - __bfloat162float(h));
            }
            *(uint4*)&Ah[arow * LDS + ahalf] = Uh.u4[0];
            *(uint4*)&Ah[arow * LDS + ahalf + 8] = Uh.u4[1];
            *(uint4*)&Al[arow * LDS + ahalf] = Ul.u4[0];
            *(uint4*)&Al[arow * LDS + ahalf + 8] = Ul.u4[1];
        }
        {
            const __nv_bfloat16* ph = BhT + (long)(col0 + brow) * K + k0 + bseg;
            const __nv_bfloat16* pl = BlT + (long)(col0 + brow) * K + k0 + bseg;
            *(uint4*)&Bh[brow * LDS + bseg] = *(const uint4*)ph;
            *(uint4*)&Bl[brow * LDS + bseg] = *(const uint4*)pl;
        }
        __syncthreads();

        #pragma unroll
        for (int ks = 0; ks < 2; ks++) {
            int kc = ks * 16;
            uint32_t ah[2][4], al[2][4];
            #pragma unroll
            for (int mt = 0; mt < 2; mt++) {
                ldmx4(ah[mt], &Ah[(wm * 32 + mt * 16 + rsel) * LDS + kc + csel]);
                ldmx4(al[mt], &Al[(wm * 32 + mt * 16 + rsel) * LDS + kc + csel]);
            }
            uint32_t bh[2][4], bl[2][4];
            #pragma unroll
            for (int gq = 0; gq < 2; gq++) {
                ldmx4(bh[gq], &Bh[(wn * 32 + gq * 16 + rsel) * LDS + kc + csel]);
                ldmx4(bl[gq], &Bl[(wn * 32 + gq * 16 + rsel) * LDS + kc + csel]);
            }
            #pragma unroll
            for (int nt = 0; nt < 4; nt++) {
                int gq = nt >> 1, hf = nt & 1;
                uint32_t bfh[2] = { bh[gq][hf], bh[gq][2 + hf] };
                uint32_t bfl[2] = { bl[gq][hf], bl[gq][2 + hf] };
                #pragma unroll
                for (int mt = 0; mt < 2; mt++) {
                    mma16816(d[mt][nt], ah[mt], bfh);
                    mma16816(d[mt][nt], ah[mt], bfl);
                    mma16816(d[mt][nt], al[mt], bfh);
                }
            }
        }
    }

    #pragma unroll
    for (int mt = 0; mt < 2; mt++) {
        int r = row0 + wm * 32 + mt * 16 + g;
        #pragma unroll
        for (int nt = 0; nt < 4; nt++) {
            int c = col0 + wn * 32 + nt * 8 + 2 * tg;
            if (r < n)
                *(float2*)(out + (long)r * CO + c) = make_float2(d[mt][nt][0], d[mt][nt][1]);
            if (r + 8 < n)
                *(float2*)(out + (long)(r + 8) * CO + c) = make_float2(d[mt][nt][2], d[mt][nt][3]);
        }
    }
}

// ---------------- BN column stats (slot-indexed) ----------------
template <int C>
__global__ void k_stats(const float* __restrict__ in, int n, int slot) {
    constexpr int RL = 256 / C;
    int col = threadIdx.x % C;
    int rl = threadIdx.x / C;
    int r0 = blockIdx.x * 256;
    int rend = r0 + 256; if (rend > n) rend = n;
    float s = 0.0f, ss = 0.0f;
    for (int r = r0 + rl; r < rend; r += RL) {
        float v = in[(long)r * C + col];
        s += v; ss += v * v;
    }
    atomicAdd(&g_ssum[slot * DD + col], s);
    atomicAdd(&g_ssq[slot * DD + col], ss);
}

// ---------------- BN normalize (+optional leaky relu) ----------------
template <int C, bool LEAKY>
__global__ void k_norm(const float* __restrict__ in, float* __restrict__ out,
                       const float* __restrict__ gamma, const float* __restrict__ beta,
                       int n, int slot)
{
    __shared__ float sc[C], sh[C];
    if (threadIdx.x < C) {
        float fn = (float)n;
        float mu = g_ssum[slot * DD + threadIdx.x] / fn;
        float var = g_ssq[slot * DD + threadIdx.x] / fn - mu * mu;
        float scale = gamma[threadIdx.x] * rsqrtf(var + 1e-5f);
        sc[threadIdx.x] = scale;
        sh[threadIdx.x] = beta[threadIdx.x] - mu * scale;
    }
    __syncthreads();
    long total4 = (long)n * C / 4;
    long idx = (long)blockIdx.x * blockDim.x + threadIdx.x;
    if (idx >= total4) return;
    float4 v = ((const float4*)in)[idx];
    int cb = (int)((idx * 4) % C);
    float r0 = v.x * sc[cb + 0] + sh[cb + 0];
    float r1 = v.y * sc[cb + 1] + sh[cb + 1];
    float r2 = v.z * sc[cb + 2] + sh[cb + 2];
    float r3 = v.w * sc[cb + 3] + sh[cb + 3];
    if (LEAKY) {
        r0 = r0 > 0.f ? r0 : 0.01f * r0;
        r1 = r1 > 0.f ? r1 : 0.01f * r1;
        r2 = r2 > 0.f ? r2 : 0.01f * r2;
        r3 = r3 > 0.f ? r3 : 0.01f * r3;
    }
    ((float4*)out)[idx] = make_float4(r0, r1, r2, r3);
}

// ---------------- edge pass 1: logits + segment max ----------------
__global__ void k_edge_logit(const void* __restrict__ eidx, long E) {
    long g = (long)blockIdx.x * blockDim.x + threadIdx.x;
    long e = g >> 3;
    int l8 = (int)(g & 7);
    if (e >= E) return;
    int i = load_idx(eidx, e);
    int j = load_idx(eidx, E + e);
    const float4* a = (const float4*)(g_su + (long)i * HH) + l8 * 2;
    const float4* b = (const float4*)(g_su + (long)j * HH) + l8 * 2;
    float4 a0 = a[0], a1 = a[1], b0 = b[0], b1 = b[1];
    float d0 = a0.x - b0.x, d1 = a0.y - b0.y, d2 = a0.z - b0.z, d3 = a0.w - b0.w;
    float d4 = a1.x - b1.x, d5 = a1.y - b1.y, d6 = a1.z - b1.z, d7 = a1.w - b1.w;
    float acc = d0 * d0 + d1 * d1 + d2 * d2 + d3 * d3
              + d4 * d4 + d5 * d5 + d6 * d6 + d7 * d7;
    unsigned int gmask = 0xFFu << (threadIdx.x & 24);
    acc += __shfl_xor_sync(gmask, acc, 1);
    acc += __shfl_xor_sync(gmask, acc, 2);
    acc += __shfl_xor_sync(gmask, acc, 4);
    if (l8 == 0) {
        float lg = -acc;
        g_ew[e] = lg;
        atomicMin((unsigned int*)&g_m[i], __float_as_uint(lg));
    }
}

// ---------------- edge pass 2 (fused): denom += ex; agg[i] += ex*xu[j] ----
__device__ __forceinline__ void red_add_v4(float* p, float4 v) {
    asm volatile("red.global.add.v4.f32 [%0], {%1,%2,%3,%4};"
                 :: "l"(p), "f"(v.x), "f"(v.y), "f"(v.z), "f"(v.w) : "memory");
}
__global__ void k_edge_expagg(const void* __restrict__ eidx, long E) {
    long g = (long)blockIdx.x * blockDim.x + threadIdx.x;
    long e = g >> 3;
    int l8 = (int)(g & 7);
    if (e >= E) return;
    int i = load_idx(eidx, e);
    int j = load_idx(eidx, E + e);
    unsigned int gmask = 0xFFu << (threadIdx.x & 24);
    float ex = 0.0f;
    if (l8 == 0) {
        ex = expf(g_ew[e] - g_m[i]);
        atomicAdd(&g_denom[i], ex);
    }
    ex = __shfl_sync(gmask, ex, (threadIdx.x & 31) & ~7);
    const float4* src = (const float4*)(g_xu + (long)j * HH) + l8 * 2;
    float* dst = g_agg + (long)i * HH + l8 * 8;
    float4 v0 = src[0], v1 = src[1];
    v0.x *= ex; v0.y *= ex; v0.z *= ex; v0.w *= ex;
    v1.x *= ex; v1.y *= ex; v1.z *= ex; v1.w *= ex;
    red_add_v4(dst, v0);
    red_add_v4(dst + 4, v1);
}

// ---------------- launch ----------------
extern "C" void kernel_launch(void* const* d_in, const int* in_sizes, int n_in,
                              void* d_out, int out_size) {
    const float* x   = (const float*)d_in[0];
    const float* y   = (const float*)d_in[1];
    const void*  eix = d_in[3];
    const float* Wu  = (const float*)d_in[4];
    const float* gu  = (const float*)d_in[5];
    const float* bu  = (const float*)d_in[6];
    const float* Wp  = (const float*)d_in[7];
    const float* gp  = (const float*)d_in[8];
    const float* bp  = (const float*)d_in[9];
    const float* cM  = (const float*)d_in[10];
    const float* Wm  = (const float*)d_in[11];
    const float* gm  = (const float*)d_in[12];
    const float* bm  = (const float*)d_in[13];
    const float* Wf  = (const float*)d_in[14];
    const float* gf  = (const float*)d_in[15];
    const float* bf  = (const float*)d_in[16];
    float* out = (float*)d_out;

    int n = in_sizes[0] / DD;
    long E = (long)in_sizes[3] / 2;

    float *xu, *su, *agg, *h1, *t2, *t3, *A12;
    cudaGetSymbolAddress((void**)&xu, g_xu);
    cudaGetSymbolAddress((void**)&su, g_su);
    cudaGetSymbolAddress((void**)&agg, g_agg);
    cudaGetSymbolAddress((void**)&h1, g_h1);
    cudaGetSymbolAddress((void**)&t2, g_t2);
    cudaGetSymbolAddress((void**)&t3, g_t3);
    cudaGetSymbolAddress((void**)&A12, g_A12);
    __nv_bfloat16 *WuhT, *WulT, *WphT, *WplT, *A12hT, *A12lT, *WmhT, *WmlT, *WfhT, *WflT;
    cudaGetSymbolAddress((void**)&WuhT, g_WuhT); cudaGetSymbolAddress((void**)&WulT, g_WulT);
    cudaGetSymbolAddress((void**)&WphT, g_WphT); cudaGetSymbolAddress((void**)&WplT, g_WplT);
    cudaGetSymbolAddress((void**)&A12hT, g_A12hT); cudaGetSymbolAddress((void**)&A12lT, g_A12lT);
    cudaGetSymbolAddress((void**)&WmhT, g_WmhT); cudaGetSymbolAddress((void**)&WmlT, g_WmlT);
    cudaGetSymbolAddress((void**)&WfhT, g_WfhT); cudaGetSymbolAddress((void**)&WflT, g_WflT);

    int rb = (n + 127) / 128;
    int sb = (n + 255) / 256;
    long init_total = (long)n * HH + 2L * n + 8L * DD;
    int ib = (int)((init_total + 255) / 256);
    int eb8 = (int)((E * 8 + 255) / 256);
    int nb64 = (int)(((long)n * HH / 4 + 255) / 256);
    int nb256 = (int)(((long)n * DD / 4 + 255) / 256);

    // launches 1-5 (ncu -s 5 -c 1 captures launch #6 = the xu GEMM)
    k_detect<<<1, 32>>>((const unsigned int*)eix);
    k_init<<<ib, 256>>>(n);
    k_prep_crf<<<1, 256>>>(cM);
    k_wprep<256, 64><<<(256 * 64 + 255) / 256, 256>>>(Wu, WuhT, WulT);
    k_wprep<256, 64><<<(256 * 64 + 255) / 256, 256>>>(Wp, WphT, WplT);

    // #6: xu = x @ Wu  (stats slot 0)
    k_mm<256, 64, false, false><<<rb, 256>>>(x, nullptr, WuhT, WulT, xu, n);
    k_stats<64><<<sb, 256>>>(xu, n, 0);
    k_norm<64, false><<<nb64, 256>>>(xu, xu, gu, bu, n, 0);

    // su = y @ Wp  (slot 1)
    k_mm<256, 64, false, false><<<rb, 256>>>(y, nullptr, WphT, WplT, su, n);
    k_stats<64><<<sb, 256>>>(su, n, 1);
    k_norm<64, false><<<nb64, 256>>>(su, su, gp, bp, n, 1);

    // edge softmax + aggregation
    k_edge_logit<<<eb8, 256>>>(eix, E);
    k_edge_expagg<<<eb8, 256>>>(eix, E);

    // h1 = cat(xu, agg/denom) @ [Minv ; C Minv]
    k_wprep<128, 64><<<(128 * 64 + 255) / 256, 256>>>(A12, A12hT, A12lT);
    k_mm<128, 64, true, true><<<rb, 256>>>(xu, agg, A12hT, A12lT, h1, n);

    // t2 = h1 @ Wm ; h2 = leakyBN(t2) in place  (slot 2)
    k_wprep<64, 256><<<(64 * 256 + 255) / 256, 256>>>(Wm, WmhT, WmlT);
    k_mm<64, 256, false, false><<<dim3(rb, 4), 256>>>(h1, nullptr, WmhT, WmlT, t2, n);
    k_stats<256><<<sb, 256>>>(t2, n, 2);
    k_norm<256, true><<<nb256, 256>>>(t2, t2, gm, bm, n, 2);

    // t3 = cat(h2, y) @ Wf ; out = leakyBN(t3)  (slot 3)
    k_wprep<512, 256><<<(512 * 256 + 255) / 256, 256>>>(Wf, WfhT, WflT);
    k_mm<512, 256, true, false><<<dim3(rb, 4), 256>>>(t2, y, WfhT, WflT, t3, n);
    k_stats<256><<<sb, 256>>>(t3, n, 3);
    k_norm<256, true><<<nb256, 256>>>(t3, out, gf, bf, n, 3);
}